// round 16
// baseline (speedup 1.0000x reference)
#include <cuda_runtime.h>
#include <cuda_bf16.h>
#include <cuda_fp16.h>
#include <math.h>
#include <stdint.h>

#define N_TOK   4096
#define D_MODEL 1024
#define N_HEADS 16
#define HEAD_DIM 64

// 0.125 * log2(e): folded into Q at projection time so attention can use exp2.
#define Q_PRESCALE 0.18033688011112042f
#define ONES_H2 0x3C003C00u   // fp16x2 (1.0, 1.0)

// ---------------- device scratch (allocation-free rule) ----------------
__device__ __half g_xh[N_TOK * D_MODEL];
__device__ __half g_wh[4][D_MODEL * D_MODEL];
__device__ __half g_q[N_TOK * D_MODEL];
__device__ __half g_k[N_TOK * D_MODEL];
__device__ __half g_v[N_TOK * D_MODEL];
__device__ __half g_c[N_TOK * D_MODEL];

// ---------------- PTX helpers (sm_80-compatible; NO tcgen05) ------------
__device__ __forceinline__ uint32_t smem_u32(const void* p) {
    uint32_t a;
    asm("{ .reg .u64 t; cvta.to.shared.u64 t, %1; cvt.u32.u64 %0, t; }" : "=r"(a) : "l"(p));
    return a;
}

#define CP16(s, g) \
    asm volatile("cp.async.cg.shared.global [%0], [%1], 16;" :: "r"(s), "l"(g))
#define CP_COMMIT() asm volatile("cp.async.commit_group;" ::: "memory")
#define CP_WAIT(n)  asm volatile("cp.async.wait_group %0;" :: "n"(n) : "memory")

#define LDMX4(r, addr) \
    asm volatile("ldmatrix.sync.aligned.m8n8.x4.shared.b16 {%0,%1,%2,%3}, [%4];" \
        : "=r"((r)[0]), "=r"((r)[1]), "=r"((r)[2]), "=r"((r)[3]) : "r"(addr))

#define LDMX4T(r, addr) \
    asm volatile("ldmatrix.sync.aligned.m8n8.x4.trans.shared.b16 {%0,%1,%2,%3}, [%4];" \
        : "=r"((r)[0]), "=r"((r)[1]), "=r"((r)[2]), "=r"((r)[3]) : "r"(addr))

#define MMA_F16(d, a, b0, b1) \
    asm volatile("mma.sync.aligned.m16n8k16.row.col.f32.f16.f16.f32 " \
        "{%0,%1,%2,%3}, {%4,%5,%6,%7}, {%8,%9}, {%0,%1,%2,%3};" \
        : "+f"((d)[0]), "+f"((d)[1]), "+f"((d)[2]), "+f"((d)[3]) \
        : "r"((a)[0]), "r"((a)[1]), "r"((a)[2]), "r"((a)[3]), "r"(b0), "r"(b1))

__device__ __forceinline__ uint32_t pack_h2(float a, float b) {
    uint32_t r;
    asm("cvt.rn.f16x2.f32 %0, %1, %2;" : "=r"(r) : "f"(b), "f"(a));
    return r;
}
__device__ __forceinline__ uint32_t ex2_h2(uint32_t x) {
    uint32_t r;
    asm("ex2.approx.f16x2 %0, %1;" : "=r"(r) : "r"(x));
    return r;
}
__device__ __forceinline__ float ex2(float x) {
    float r; asm("ex2.approx.f32 %0, %1;" : "=f"(r) : "f"(x)); return r;
}
__device__ __forceinline__ float rcp(float x) {
    float r; asm("rcp.approx.f32 %0, %1;" : "=f"(r) : "f"(x)); return r;
}

// ---------------------------------------------------------------------------
// convert fp32 -> fp16: one fused launch. grid (1024, 8):
// y 0..3 -> weights, y 4..7 -> quarter of x.
// ---------------------------------------------------------------------------
__global__ __launch_bounds__(256) void conv_all_kernel(
    const float* __restrict__ x,
    const float* __restrict__ w0, const float* __restrict__ w1,
    const float* __restrict__ w2, const float* __restrict__ w3)
{
    const int sel = blockIdx.y;
    const size_t NW = (size_t)D_MODEL * D_MODEL;
    const float* src;
    __half* dst;
    if (sel < 4) {
        src = (sel == 0) ? w0 : (sel == 1) ? w1 : (sel == 2) ? w2 : w3;
        dst = &g_wh[0][0] + sel * NW;
    } else {
        src = x + (size_t)(sel - 4) * NW;
        dst = g_xh + (size_t)(sel - 4) * NW;
    }
    int i = (blockIdx.x * 256 + threadIdx.x) * 4;
    float4 v = *(const float4*)(src + i);
    uint32_t* pd = (uint32_t*)(dst + i);
    pd[0] = pack_h2(v.x, v.y);
    pd[1] = pack_h2(v.z, v.w);
}

// ---------------------------------------------------------------------------
// HMMA fp16 single-pass GEMM core: acc += A[m][k]*B[n][k] (fp32 accum).
// CTA 128x128, BK=64, 256 threads (8 warps, 32m x 64n).
// 2-stage cp.async pipeline (32KB stages: A 16K | B 16K), ONE barrier per
// 64-wide K-step (16 barriers total). Rows are 128B = 8 x 16B chunks,
// swizzle phys_chunk = chunk ^ (row & 7) -> ldmatrix conflict-free.
// ---------------------------------------------------------------------------
#define GSTAGE 32768
#define GSMEM  (2 * GSTAGE)
#define NCHUNK 16

__device__ __forceinline__ void load_chunk(
    uint32_t sbase, int tid, int m0, int n0, int kc,
    const __half* __restrict__ A, const __half* __restrict__ B)
{
    const int row = tid >> 1;              // 0..127
    const int cbase = (tid & 1) * 4;       // chunks 0-3 or 4-7
    const int kcol = kc * 64 + cbase * 8;
#pragma unroll
    for (int j = 0; j < 4; j++) {
        const int chunk = cbase + j;
        const uint32_t so = (uint32_t)(row * 128 + ((chunk ^ (row & 7)) << 4));
        CP16(sbase + so,         (const char*)(A + (size_t)(m0 + row) * 1024 + kcol + j * 8));
        CP16(sbase + 16384 + so, (const char*)(B + (size_t)(n0 + row) * 1024 + kcol + j * 8));
    }
}

__device__ __forceinline__ void gemm_core(
    uint32_t sb, int tid, int m0, int n0,
    const __half* __restrict__ A, const __half* __restrict__ B,
    float acc[2][8][4])
{
    const int wid = tid >> 5;
    const int lid = tid & 31;
    const int warp_m = (wid >> 1) * 32;
    const int warp_n = (wid & 1) * 64;
    const int sub = lid >> 3;
    const int r8  = lid & 7;

    load_chunk(sb, tid, m0, n0, 0, A, B);
    CP_COMMIT();

    for (int kc = 0; kc < NCHUNK; kc++) {
        CP_WAIT(0);
        __syncthreads();
        if (kc + 1 < NCHUNK) {
            load_chunk(sb + (uint32_t)((kc + 1) & 1) * GSTAGE, tid, m0, n0, kc + 1, A, B);
            CP_COMMIT();
        }
        const uint32_t cur = sb + (uint32_t)(kc & 1) * GSTAGE;

#pragma unroll
        for (int ks = 0; ks < 4; ks++) {
            const int kchunk = ks * 2 + (sub >> 1);
            uint32_t af[2][4], bf[4][4];
#pragma unroll
            for (int mt = 0; mt < 2; mt++) {
                const int mr = warp_m + mt * 16 + ((sub & 1) << 3) + r8;
                LDMX4(af[mt], cur + (uint32_t)(mr * 128 + ((kchunk ^ (mr & 7)) << 4)));
            }
#pragma unroll
            for (int nt = 0; nt < 4; nt++) {
                const int nr = warp_n + nt * 16 + ((sub & 1) << 3) + r8;
                LDMX4(bf[nt], cur + 16384 + (uint32_t)(nr * 128 + ((kchunk ^ (nr & 7)) << 4)));
            }
#pragma unroll
            for (int mt = 0; mt < 2; mt++)
#pragma unroll
                for (int nt = 0; nt < 4; nt++) {
                    MMA_F16(acc[mt][2 * nt + 0], af[mt], bf[nt][0], bf[nt][2]);
                    MMA_F16(acc[mt][2 * nt + 1], af[mt], bf[nt][1], bf[nt][3]);
                }
        }
    }
}

// Fused QKV projection: grid (24, 32); blockIdx.x -> {sel, n-block}.
__global__ __launch_bounds__(256) void gemm_qkv_kernel()
{
    extern __shared__ __align__(128) char smem[];
    const uint32_t sb = smem_u32(smem);
    const int tid = threadIdx.x;
    const int sel = blockIdx.x >> 3;
    const int n0 = (blockIdx.x & 7) * 128;
    const int m0 = blockIdx.y * 128;
    const size_t NW = (size_t)D_MODEL * D_MODEL;

    const __half* W = &g_wh[0][0] + sel * NW;
    __half* C = (sel == 0) ? g_q : (sel == 1) ? g_k : g_v;
    const float scale = (sel == 0) ? Q_PRESCALE : 1.0f;

    float acc[2][8][4];
#pragma unroll
    for (int a = 0; a < 2; a++)
#pragma unroll
        for (int b = 0; b < 8; b++)
#pragma unroll
            for (int c = 0; c < 4; c++) acc[a][b][c] = 0.f;

    gemm_core(sb, tid, m0, n0, g_xh, W, acc);

    const int wid = tid >> 5, lid = tid & 31;
    const int warp_m = (wid >> 1) * 32, warp_n = (wid & 1) * 64;
#pragma unroll
    for (int mt = 0; mt < 2; mt++) {
        const int mrow = m0 + warp_m + mt * 16 + (lid >> 2);
#pragma unroll
        for (int nt = 0; nt < 8; nt++) {
            const int ncol = n0 + warp_n + nt * 8 + 2 * (lid & 3);
            *(uint32_t*)(C + (size_t)mrow * 1024 + ncol) =
                pack_h2(acc[mt][nt][0] * scale, acc[mt][nt][1] * scale);
            *(uint32_t*)(C + (size_t)(mrow + 8) * 1024 + ncol) =
                pack_h2(acc[mt][nt][2] * scale, acc[mt][nt][3] * scale);
        }
    }
}

// Output projection: fp32 out + bias.
__global__ __launch_bounds__(256) void gemm_out_kernel(
    const float* __restrict__ bias, float* __restrict__ C)
{
    extern __shared__ __align__(128) char smem[];
    const uint32_t sb = smem_u32(smem);
    const int tid = threadIdx.x;
    const int n0 = blockIdx.x * 128;
    const int m0 = blockIdx.y * 128;
    const size_t NW = (size_t)D_MODEL * D_MODEL;

    float acc[2][8][4];
#pragma unroll
    for (int a = 0; a < 2; a++)
#pragma unroll
        for (int b = 0; b < 8; b++)
#pragma unroll
            for (int c = 0; c < 4; c++) acc[a][b][c] = 0.f;

    gemm_core(sb, tid, m0, n0, g_c, &g_wh[0][0] + 3 * NW, acc);

    const int wid = tid >> 5, lid = tid & 31;
    const int warp_m = (wid >> 1) * 32, warp_n = (wid & 1) * 64;
#pragma unroll
    for (int mt = 0; mt < 2; mt++) {
        const int mrow = m0 + warp_m + mt * 16 + (lid >> 2);
#pragma unroll
        for (int nt = 0; nt < 8; nt++) {
            const int ncol = n0 + warp_n + nt * 8 + 2 * (lid & 3);
            const float b0 = bias[ncol], b1 = bias[ncol + 1];
            *(float2*)(C + (size_t)mrow * 1024 + ncol) =
                make_float2(acc[mt][nt][0] + b0, acc[mt][nt][1] + b1);
            *(float2*)(C + (size_t)(mrow + 8) * 1024 + ncol) =
                make_float2(acc[mt][nt][2] + b0, acc[mt][nt][3] + b1);
        }
    }
}

// ---------------------------------------------------------------------------
// Tensor-core flash attention (causal), full fp16. CTA = TWO q-blocks
// {63-p, p} (constant 65 K-tiles). 128 threads, launch_bounds(128,3).
// QK^T / PV: 1-pass fp16. Softmax: fp16x2 MUFU exp2 (P emerges MMA-ready),
// row sums accumulated EXACTLY in fp32 via MMA against a ones B-fragment.
// 2-stage cp.async, 16KB stages (K 8K | V 8K), ONE barrier per tile.
// ---------------------------------------------------------------------------
#define A_STSZ 16384
#define A_VF   8192
#define A_SMEM (2 * A_STSZ)   // 32768

__device__ __forceinline__ uint32_t aphys(int row, int chunk) {
    return (uint32_t)(row * 128 + (((chunk) ^ (row & 7)) << 4));
}

__device__ __forceinline__ void attn_load_kv(uint32_t st, int kb, int h, int tid) {
    const int r0 = tid >> 3;
    const int c  = tid & 7;
#pragma unroll
    for (int u = 0; u < 4; u++) {
        const int r = r0 + u * 16;
        const uint32_t so = aphys(r, c);
        const size_t gi = (size_t)(kb * 64 + r) * 1024 + h * 64 + c * 8;
        CP16(st + so,        (const char*)(g_k + gi));
        CP16(st + A_VF + so, (const char*)(g_v + gi));
    }
}

__global__ __launch_bounds__(128, 3) void attn_kernel()
{
    extern __shared__ __align__(128) char smem[];
    const uint32_t sb = smem_u32(smem);
    const int tid = threadIdx.x;
    const int w = tid >> 5;
    const int l = tid & 31;
    const int p = blockIdx.x;           // 0..31 (pair index)
    const int h = blockIdx.y;

#pragma unroll 1
    for (int half = 0; half < 2; half++) {
        const int qb = half ? p : (63 - p);   // long block first
        const int q0 = qb * 64;
        const int nkt = qb + 1;

        // Prologue: Q (8KB) into stage-1 K region; KV tile 0 into stage-0.
        {
            const int r0 = tid >> 3;
            const int c  = tid & 7;
#pragma unroll
            for (int u = 0; u < 4; u++) {
                const int r = r0 + u * 16;
                const uint32_t so = aphys(r, c);
                CP16(sb + A_STSZ + so,
                     (const char*)(g_q + (size_t)(q0 + r) * 1024 + h * 64 + c * 8));
            }
        }
        attn_load_kv(sb, 0, h, tid);
        CP_COMMIT();
        CP_WAIT(0);
        __syncthreads();

        // Consume Q into register fragments, then free the stage-1 region.
        uint32_t qf[4][4];
        {
            const int row = 16 * w + (l & 15);
#pragma unroll
            for (int ks = 0; ks < 4; ks++)
                LDMX4(qf[ks], sb + A_STSZ + aphys(row, 2 * ks + (l >> 4)));
        }
        __syncthreads();

        float O[8][4];
        float lsum[4];
        float m0 = -INFINITY, m1 = -INFINITY;
#pragma unroll
        for (int nt = 0; nt < 8; nt++)
#pragma unroll
            for (int j = 0; j < 4; j++) O[nt][j] = 0.f;
#pragma unroll
        for (int j = 0; j < 4; j++) lsum[j] = 0.f;

        for (int kb = 0; kb < nkt; kb++) {
            if (kb > 0) {
                CP_WAIT(0);
                __syncthreads();
            }
            if (kb + 1 < nkt) {
                attn_load_kv(sb + (uint32_t)((kb + 1) & 1) * A_STSZ, kb + 1, h, tid);
                CP_COMMIT();
            }
            const uint32_t st = sb + (uint32_t)(kb & 1) * A_STSZ;

            // ---- S = Q K^T (single-pass fp16) ----
            float s[8][4];
#pragma unroll
            for (int nt = 0; nt < 8; nt++)
#pragma unroll
                for (int j = 0; j < 4; j++) s[nt][j] = 0.f;

#pragma unroll
            for (int ks = 0; ks < 4; ks++) {
#pragma unroll
                for (int ntp = 0; ntp < 4; ntp++) {
                    const int nrow = ntp * 16 + (l & 15);
                    uint32_t bh[4];
                    LDMX4(bh, st + aphys(nrow, 2 * ks + (l >> 4)));
                    MMA_F16(s[2 * ntp + 0], qf[ks], bh[0], bh[2]);
                    MMA_F16(s[2 * ntp + 1], qf[ks], bh[1], bh[3]);
                }
            }

            // ---- causal mask (diagonal tile only) ----
            if (kb == qb) {
                const int rl0 = 16 * w + (l >> 2);
#pragma unroll
                for (int nt = 0; nt < 8; nt++) {
                    const int c0 = nt * 8 + 2 * (l & 3);
                    if (c0     > rl0    ) s[nt][0] = -INFINITY;
                    if (c0 + 1 > rl0    ) s[nt][1] = -INFINITY;
                    if (c0     > rl0 + 8) s[nt][2] = -INFINITY;
                    if (c0 + 1 > rl0 + 8) s[nt][3] = -INFINITY;
                }
            }

            // ---- online max (rows l>>2 and l>>2 + 8) ----
            float mr0 = -INFINITY, mr1 = -INFINITY;
#pragma unroll
            for (int nt = 0; nt < 8; nt++) {
                mr0 = fmaxf(mr0, fmaxf(s[nt][0], s[nt][1]));
                mr1 = fmaxf(mr1, fmaxf(s[nt][2], s[nt][3]));
            }
            mr0 = fmaxf(mr0, __shfl_xor_sync(0xffffffffu, mr0, 1));
            mr0 = fmaxf(mr0, __shfl_xor_sync(0xffffffffu, mr0, 2));
            mr1 = fmaxf(mr1, __shfl_xor_sync(0xffffffffu, mr1, 1));
            mr1 = fmaxf(mr1, __shfl_xor_sync(0xffffffffu, mr1, 2));
            const float mn0 = fmaxf(m0, mr0);
            const float mn1 = fmaxf(m1, mr1);
            const float a0 = ex2(m0 - mn0);
            const float a1 = ex2(m1 - mn1);
            m0 = mn0; m1 = mn1;

            // ---- rescale O and lsum ----
#pragma unroll
            for (int nt = 0; nt < 8; nt++) {
                O[nt][0] *= a0; O[nt][1] *= a0;
                O[nt][2] *= a1; O[nt][3] *= a1;
            }
            lsum[0] *= a0; lsum[1] *= a0;
            lsum[2] *= a1; lsum[3] *= a1;

            // ---- P = exp2(s - mn) directly in fp16x2; row sums via MMA ----
#pragma unroll
            for (int ks = 0; ks < 4; ks++) {
                uint32_t ph[4];
                ph[0] = ex2_h2(pack_h2(s[2 * ks][0] - mn0,     s[2 * ks][1] - mn0));
                ph[1] = ex2_h2(pack_h2(s[2 * ks][2] - mn1,     s[2 * ks][3] - mn1));
                ph[2] = ex2_h2(pack_h2(s[2 * ks + 1][0] - mn0, s[2 * ks + 1][1] - mn0));
                ph[3] = ex2_h2(pack_h2(s[2 * ks + 1][2] - mn1, s[2 * ks + 1][3] - mn1));

                MMA_F16(lsum, ph, ONES_H2, ONES_H2);   // exact fp32 row sums

                const int vrow = 16 * ks + (l & 15);
#pragma unroll
                for (int dtp = 0; dtp < 4; dtp++) {
                    uint32_t vf[4];
                    LDMX4T(vf, st + A_VF + aphys(vrow, 2 * dtp + (l >> 4)));
                    MMA_F16(O[2 * dtp + 0], ph, vf[0], vf[1]);
                    MMA_F16(O[2 * dtp + 1], ph, vf[2], vf[3]);
                }
            }
        }

        // ---- epilogue: ctx fp16 ----
        const float i0 = rcp(lsum[0]);
        const float i1 = rcp(lsum[2]);
        const int rg0 = q0 + 16 * w + (l >> 2);
        const int cb = h * 64 + 2 * (l & 3);
#pragma unroll
        for (int nt = 0; nt < 8; nt++) {
            const size_t o0 = (size_t)rg0 * 1024 + cb + nt * 8;
            const size_t o1 = (size_t)(rg0 + 8) * 1024 + cb + nt * 8;
            *(uint32_t*)(g_c + o0) = pack_h2(O[nt][0] * i0, O[nt][1] * i0);
            *(uint32_t*)(g_c + o1) = pack_h2(O[nt][2] * i1, O[nt][3] * i1);
        }
        // Barrier between halves: all warps must finish reading the last KV
        // stage before the next half's prologue overwrites both stages.
        __syncthreads();
    }
}

// ---------------------------------------------------------------------------
extern "C" void kernel_launch(void* const* d_in, const int* in_sizes, int n_in,
                              void* d_out, int out_size)
{
    const float* x  = (const float*)d_in[0];
    const float* Wq = (const float*)d_in[1];
    const float* Wk = (const float*)d_in[2];
    const float* Wv = (const float*)d_in[3];
    const float* Wo = (const float*)d_in[4];
    const float* bo = (const float*)d_in[5];
    float* out = (float*)d_out;

    const int NW = D_MODEL * D_MODEL;     // 1M

    conv_all_kernel<<<dim3(NW / 1024, 8), 256>>>(x, Wq, Wk, Wv, Wo);

    cudaFuncSetAttribute(gemm_qkv_kernel, cudaFuncAttributeMaxDynamicSharedMemorySize, GSMEM);
    cudaFuncSetAttribute(gemm_out_kernel, cudaFuncAttributeMaxDynamicSharedMemorySize, GSMEM);

    gemm_qkv_kernel<<<dim3(24, 32), 256, GSMEM>>>();

    cudaFuncSetAttribute(attn_kernel, cudaFuncAttributeMaxDynamicSharedMemorySize, A_SMEM);
    attn_kernel<<<dim3(32, N_HEADS), 128, A_SMEM>>>();

    gemm_out_kernel<<<dim3(8, 32), 256, GSMEM>>>(bo, out);
}

// round 17
// speedup vs baseline: 1.0777x; 1.0777x over previous
#include <cuda_runtime.h>
#include <cuda_bf16.h>
#include <cuda_fp16.h>
#include <math.h>
#include <stdint.h>

#define N_TOK   4096
#define D_MODEL 1024
#define N_HEADS 16
#define HEAD_DIM 64

// 0.125 * log2(e): folded into Q at projection time so attention can use exp2.
#define Q_PRESCALE 0.18033688011112042f
#define ONES_H2 0x3C003C00u   // fp16x2 (1.0, 1.0)

// ---------------- device scratch (allocation-free rule) ----------------
__device__ __half g_xh[N_TOK * D_MODEL];
__device__ __half g_wh[4][D_MODEL * D_MODEL];
__device__ __half g_q[N_TOK * D_MODEL];
__device__ __half g_k[N_TOK * D_MODEL];
__device__ __half g_v[N_TOK * D_MODEL];
__device__ __half g_c[N_TOK * D_MODEL];

// ---------------- PTX helpers (sm_80-compatible; NO tcgen05) ------------
__device__ __forceinline__ uint32_t smem_u32(const void* p) {
    uint32_t a;
    asm("{ .reg .u64 t; cvta.to.shared.u64 t, %1; cvt.u32.u64 %0, t; }" : "=r"(a) : "l"(p));
    return a;
}

#define CP16(s, g) \
    asm volatile("cp.async.cg.shared.global [%0], [%1], 16;" :: "r"(s), "l"(g))
#define CP_COMMIT() asm volatile("cp.async.commit_group;" ::: "memory")
#define CP_WAIT(n)  asm volatile("cp.async.wait_group %0;" :: "n"(n) : "memory")

#define LDMX4(r, addr) \
    asm volatile("ldmatrix.sync.aligned.m8n8.x4.shared.b16 {%0,%1,%2,%3}, [%4];" \
        : "=r"((r)[0]), "=r"((r)[1]), "=r"((r)[2]), "=r"((r)[3]) : "r"(addr))

#define LDMX4T(r, addr) \
    asm volatile("ldmatrix.sync.aligned.m8n8.x4.trans.shared.b16 {%0,%1,%2,%3}, [%4];" \
        : "=r"((r)[0]), "=r"((r)[1]), "=r"((r)[2]), "=r"((r)[3]) : "r"(addr))

#define MMA_F16(d, a, b0, b1) \
    asm volatile("mma.sync.aligned.m16n8k16.row.col.f32.f16.f16.f32 " \
        "{%0,%1,%2,%3}, {%4,%5,%6,%7}, {%8,%9}, {%0,%1,%2,%3};" \
        : "+f"((d)[0]), "+f"((d)[1]), "+f"((d)[2]), "+f"((d)[3]) \
        : "r"((a)[0]), "r"((a)[1]), "r"((a)[2]), "r"((a)[3]), "r"(b0), "r"(b1))

__device__ __forceinline__ uint32_t pack_h2(float a, float b) {
    uint32_t r;
    asm("cvt.rn.f16x2.f32 %0, %1, %2;" : "=r"(r) : "f"(b), "f"(a));
    return r;
}
__device__ __forceinline__ uint32_t ex2_h2(uint32_t x) {
    uint32_t r;
    asm("ex2.approx.f16x2 %0, %1;" : "=r"(r) : "r"(x));
    return r;
}
__device__ __forceinline__ float ex2(float x) {
    float r; asm("ex2.approx.f32 %0, %1;" : "=f"(r) : "f"(x)); return r;
}
__device__ __forceinline__ float rcp(float x) {
    float r; asm("rcp.approx.f32 %0, %1;" : "=f"(r) : "f"(x)); return r;
}

// ---------------------------------------------------------------------------
// convert fp32 -> fp16: one fused launch. grid (1024, 8):
// y 0..3 -> weights, y 4..7 -> quarter of x.
// ---------------------------------------------------------------------------
__global__ __launch_bounds__(256) void conv_all_kernel(
    const float* __restrict__ x,
    const float* __restrict__ w0, const float* __restrict__ w1,
    const float* __restrict__ w2, const float* __restrict__ w3)
{
    const int sel = blockIdx.y;
    const size_t NW = (size_t)D_MODEL * D_MODEL;
    const float* src;
    __half* dst;
    if (sel < 4) {
        src = (sel == 0) ? w0 : (sel == 1) ? w1 : (sel == 2) ? w2 : w3;
        dst = &g_wh[0][0] + sel * NW;
    } else {
        src = x + (size_t)(sel - 4) * NW;
        dst = g_xh + (size_t)(sel - 4) * NW;
    }
    int i = (blockIdx.x * 256 + threadIdx.x) * 4;
    float4 v = *(const float4*)(src + i);
    uint32_t* pd = (uint32_t*)(dst + i);
    pd[0] = pack_h2(v.x, v.y);
    pd[1] = pack_h2(v.z, v.w);
}

// ---------------------------------------------------------------------------
// HMMA fp16 single-pass GEMM core: acc += A[m][k]*B[n][k] (fp32 accum).
// CTA 128x128, BK=32, 256 threads (8 warps, 32m x 64n).
// 3-stage cp.async pipeline (16KB stages: A 8K | B 8K):
//   wait(1) [chunk kc landed] -> sync -> issue chunk kc+2 -> compute kc.
// Each load gets ~2 compute phases to complete; wait never blocks on the
// newest load.
// ---------------------------------------------------------------------------
#define GSTAGE 16384
#define GSMEM  (3 * GSTAGE)
#define NCHUNK 32

__device__ __forceinline__ void load_chunk(
    uint32_t sbase, int tid, int m0, int n0, int kc,
    const __half* __restrict__ A, const __half* __restrict__ B)
{
    const int row = tid >> 2;
    const int chunk = tid & 3;
    const int kcol = kc * 32 + chunk * 8;
#pragma unroll
    for (int u = 0; u < 2; u++) {
        const int r = row + u * 64;
        const uint32_t so = (uint32_t)(r * 64 + ((chunk ^ ((r >> 1) & 3)) << 4));
        CP16(sbase + so,        (const char*)(A + (size_t)(m0 + r) * 1024 + kcol));
        CP16(sbase + 8192 + so, (const char*)(B + (size_t)(n0 + r) * 1024 + kcol));
    }
}

__device__ __forceinline__ void gemm_core(
    uint32_t sb, int tid, int m0, int n0,
    const __half* __restrict__ A, const __half* __restrict__ B,
    float acc[2][8][4])
{
    const int wid = tid >> 5;
    const int lid = tid & 31;
    const int warp_m = (wid >> 1) * 32;
    const int warp_n = (wid & 1) * 64;
    const int sub = lid >> 3;
    const int r8  = lid & 7;

    load_chunk(sb, tid, m0, n0, 0, A, B);
    CP_COMMIT();
    load_chunk(sb + GSTAGE, tid, m0, n0, 1, A, B);
    CP_COMMIT();

    uint32_t stage = 0;          // kc % 3
    for (int kc = 0; kc < NCHUNK; kc++) {
        if (kc + 1 < NCHUNK) { CP_WAIT(1); } else { CP_WAIT(0); }
        __syncthreads();
        if (kc + 2 < NCHUNK) {
            uint32_t s2 = stage + 2; if (s2 >= 3) s2 -= 3;
            load_chunk(sb + s2 * GSTAGE, tid, m0, n0, kc + 2, A, B);
            CP_COMMIT();
        }
        const uint32_t cur = sb + stage * GSTAGE;
        if (++stage == 3) stage = 0;

#pragma unroll
        for (int ks = 0; ks < 2; ks++) {
            const int kchunk = ks * 2 + (sub >> 1);
            uint32_t af[2][4], bf[4][4];
#pragma unroll
            for (int mt = 0; mt < 2; mt++) {
                const int mr = warp_m + mt * 16 + ((sub & 1) << 3) + r8;
                LDMX4(af[mt], cur + (uint32_t)(mr * 64 + ((kchunk ^ ((mr >> 1) & 3)) << 4)));
            }
#pragma unroll
            for (int nt = 0; nt < 4; nt++) {
                const int nr = warp_n + nt * 16 + ((sub & 1) << 3) + r8;
                LDMX4(bf[nt], cur + 8192 + (uint32_t)(nr * 64 + ((kchunk ^ ((nr >> 1) & 3)) << 4)));
            }
#pragma unroll
            for (int mt = 0; mt < 2; mt++)
#pragma unroll
                for (int nt = 0; nt < 4; nt++) {
                    MMA_F16(acc[mt][2 * nt + 0], af[mt], bf[nt][0], bf[nt][2]);
                    MMA_F16(acc[mt][2 * nt + 1], af[mt], bf[nt][1], bf[nt][3]);
                }
        }
    }
}

// Fused QKV projection: grid (24, 32); blockIdx.x -> {sel, n-block}.
__global__ __launch_bounds__(256) void gemm_qkv_kernel()
{
    extern __shared__ __align__(128) char smem[];
    const uint32_t sb = smem_u32(smem);
    const int tid = threadIdx.x;
    const int sel = blockIdx.x >> 3;
    const int n0 = (blockIdx.x & 7) * 128;
    const int m0 = blockIdx.y * 128;
    const size_t NW = (size_t)D_MODEL * D_MODEL;

    const __half* W = &g_wh[0][0] + sel * NW;
    __half* C = (sel == 0) ? g_q : (sel == 1) ? g_k : g_v;
    const float scale = (sel == 0) ? Q_PRESCALE : 1.0f;

    float acc[2][8][4];
#pragma unroll
    for (int a = 0; a < 2; a++)
#pragma unroll
        for (int b = 0; b < 8; b++)
#pragma unroll
            for (int c = 0; c < 4; c++) acc[a][b][c] = 0.f;

    gemm_core(sb, tid, m0, n0, g_xh, W, acc);

    const int wid = tid >> 5, lid = tid & 31;
    const int warp_m = (wid >> 1) * 32, warp_n = (wid & 1) * 64;
#pragma unroll
    for (int mt = 0; mt < 2; mt++) {
        const int mrow = m0 + warp_m + mt * 16 + (lid >> 2);
#pragma unroll
        for (int nt = 0; nt < 8; nt++) {
            const int ncol = n0 + warp_n + nt * 8 + 2 * (lid & 3);
            *(uint32_t*)(C + (size_t)mrow * 1024 + ncol) =
                pack_h2(acc[mt][nt][0] * scale, acc[mt][nt][1] * scale);
            *(uint32_t*)(C + (size_t)(mrow + 8) * 1024 + ncol) =
                pack_h2(acc[mt][nt][2] * scale, acc[mt][nt][3] * scale);
        }
    }
}

// Output projection: fp32 out + bias.
__global__ __launch_bounds__(256) void gemm_out_kernel(
    const float* __restrict__ bias, float* __restrict__ C)
{
    extern __shared__ __align__(128) char smem[];
    const uint32_t sb = smem_u32(smem);
    const int tid = threadIdx.x;
    const int n0 = blockIdx.x * 128;
    const int m0 = blockIdx.y * 128;
    const size_t NW = (size_t)D_MODEL * D_MODEL;

    float acc[2][8][4];
#pragma unroll
    for (int a = 0; a < 2; a++)
#pragma unroll
        for (int b = 0; b < 8; b++)
#pragma unroll
            for (int c = 0; c < 4; c++) acc[a][b][c] = 0.f;

    gemm_core(sb, tid, m0, n0, g_c, &g_wh[0][0] + 3 * NW, acc);

    const int wid = tid >> 5, lid = tid & 31;
    const int warp_m = (wid >> 1) * 32, warp_n = (wid & 1) * 64;
#pragma unroll
    for (int mt = 0; mt < 2; mt++) {
        const int mrow = m0 + warp_m + mt * 16 + (lid >> 2);
#pragma unroll
        for (int nt = 0; nt < 8; nt++) {
            const int ncol = n0 + warp_n + nt * 8 + 2 * (lid & 3);
            const float b0 = bias[ncol], b1 = bias[ncol + 1];
            *(float2*)(C + (size_t)mrow * 1024 + ncol) =
                make_float2(acc[mt][nt][0] + b0, acc[mt][nt][1] + b1);
            *(float2*)(C + (size_t)(mrow + 8) * 1024 + ncol) =
                make_float2(acc[mt][nt][2] + b0, acc[mt][nt][3] + b1);
        }
    }
}

// ---------------------------------------------------------------------------
// Tensor-core flash attention (causal), full fp16. CTA = TWO q-blocks
// {63-p, p} (constant 65 K-tiles). 128 threads, launch_bounds(128,3).
// QK^T / PV: 1-pass fp16. Softmax: fp16x2 MUFU exp2 (P emerges MMA-ready),
// row sums accumulated EXACTLY in fp32 via MMA against a ones B-fragment.
// 2-stage cp.async, 16KB stages (K 8K | V 8K), ONE barrier per tile.
// ---------------------------------------------------------------------------
#define A_STSZ 16384
#define A_VF   8192
#define A_SMEM (2 * A_STSZ)   // 32768

__device__ __forceinline__ uint32_t aphys(int row, int chunk) {
    return (uint32_t)(row * 128 + (((chunk) ^ (row & 7)) << 4));
}

__device__ __forceinline__ void attn_load_kv(uint32_t st, int kb, int h, int tid) {
    const int r0 = tid >> 3;
    const int c  = tid & 7;
#pragma unroll
    for (int u = 0; u < 4; u++) {
        const int r = r0 + u * 16;
        const uint32_t so = aphys(r, c);
        const size_t gi = (size_t)(kb * 64 + r) * 1024 + h * 64 + c * 8;
        CP16(st + so,        (const char*)(g_k + gi));
        CP16(st + A_VF + so, (const char*)(g_v + gi));
    }
}

__global__ __launch_bounds__(128, 3) void attn_kernel()
{
    extern __shared__ __align__(128) char smem[];
    const uint32_t sb = smem_u32(smem);
    const int tid = threadIdx.x;
    const int w = tid >> 5;
    const int l = tid & 31;
    const int p = blockIdx.x;           // 0..31 (pair index)
    const int h = blockIdx.y;

#pragma unroll 1
    for (int half = 0; half < 2; half++) {
        const int qb = half ? p : (63 - p);   // long block first
        const int q0 = qb * 64;
        const int nkt = qb + 1;

        // Prologue: Q (8KB) into stage-1 K region; KV tile 0 into stage-0.
        {
            const int r0 = tid >> 3;
            const int c  = tid & 7;
#pragma unroll
            for (int u = 0; u < 4; u++) {
                const int r = r0 + u * 16;
                const uint32_t so = aphys(r, c);
                CP16(sb + A_STSZ + so,
                     (const char*)(g_q + (size_t)(q0 + r) * 1024 + h * 64 + c * 8));
            }
        }
        attn_load_kv(sb, 0, h, tid);
        CP_COMMIT();
        CP_WAIT(0);
        __syncthreads();

        // Consume Q into register fragments, then free the stage-1 region.
        uint32_t qf[4][4];
        {
            const int row = 16 * w + (l & 15);
#pragma unroll
            for (int ks = 0; ks < 4; ks++)
                LDMX4(qf[ks], sb + A_STSZ + aphys(row, 2 * ks + (l >> 4)));
        }
        __syncthreads();

        float O[8][4];
        float lsum[4];
        float m0 = -INFINITY, m1 = -INFINITY;
#pragma unroll
        for (int nt = 0; nt < 8; nt++)
#pragma unroll
            for (int j = 0; j < 4; j++) O[nt][j] = 0.f;
#pragma unroll
        for (int j = 0; j < 4; j++) lsum[j] = 0.f;

        for (int kb = 0; kb < nkt; kb++) {
            if (kb > 0) {
                CP_WAIT(0);
                __syncthreads();
            }
            if (kb + 1 < nkt) {
                attn_load_kv(sb + (uint32_t)((kb + 1) & 1) * A_STSZ, kb + 1, h, tid);
                CP_COMMIT();
            }
            const uint32_t st = sb + (uint32_t)(kb & 1) * A_STSZ;

            // ---- S = Q K^T (single-pass fp16) ----
            float s[8][4];
#pragma unroll
            for (int nt = 0; nt < 8; nt++)
#pragma unroll
                for (int j = 0; j < 4; j++) s[nt][j] = 0.f;

#pragma unroll
            for (int ks = 0; ks < 4; ks++) {
#pragma unroll
                for (int ntp = 0; ntp < 4; ntp++) {
                    const int nrow = ntp * 16 + (l & 15);
                    uint32_t bh[4];
                    LDMX4(bh, st + aphys(nrow, 2 * ks + (l >> 4)));
                    MMA_F16(s[2 * ntp + 0], qf[ks], bh[0], bh[2]);
                    MMA_F16(s[2 * ntp + 1], qf[ks], bh[1], bh[3]);
                }
            }

            // ---- causal mask (diagonal tile only) ----
            if (kb == qb) {
                const int rl0 = 16 * w + (l >> 2);
#pragma unroll
                for (int nt = 0; nt < 8; nt++) {
                    const int c0 = nt * 8 + 2 * (l & 3);
                    if (c0     > rl0    ) s[nt][0] = -INFINITY;
                    if (c0 + 1 > rl0    ) s[nt][1] = -INFINITY;
                    if (c0     > rl0 + 8) s[nt][2] = -INFINITY;
                    if (c0 + 1 > rl0 + 8) s[nt][3] = -INFINITY;
                }
            }

            // ---- online max (rows l>>2 and l>>2 + 8) ----
            float mr0 = -INFINITY, mr1 = -INFINITY;
#pragma unroll
            for (int nt = 0; nt < 8; nt++) {
                mr0 = fmaxf(mr0, fmaxf(s[nt][0], s[nt][1]));
                mr1 = fmaxf(mr1, fmaxf(s[nt][2], s[nt][3]));
            }
            mr0 = fmaxf(mr0, __shfl_xor_sync(0xffffffffu, mr0, 1));
            mr0 = fmaxf(mr0, __shfl_xor_sync(0xffffffffu, mr0, 2));
            mr1 = fmaxf(mr1, __shfl_xor_sync(0xffffffffu, mr1, 1));
            mr1 = fmaxf(mr1, __shfl_xor_sync(0xffffffffu, mr1, 2));
            const float mn0 = fmaxf(m0, mr0);
            const float mn1 = fmaxf(m1, mr1);
            const float a0 = ex2(m0 - mn0);
            const float a1 = ex2(m1 - mn1);
            m0 = mn0; m1 = mn1;

            // ---- rescale O and lsum ----
#pragma unroll
            for (int nt = 0; nt < 8; nt++) {
                O[nt][0] *= a0; O[nt][1] *= a0;
                O[nt][2] *= a1; O[nt][3] *= a1;
            }
            lsum[0] *= a0; lsum[1] *= a0;
            lsum[2] *= a1; lsum[3] *= a1;

            // ---- P = exp2(s - mn) directly in fp16x2; row sums via MMA ----
#pragma unroll
            for (int ks = 0; ks < 4; ks++) {
                uint32_t ph[4];
                ph[0] = ex2_h2(pack_h2(s[2 * ks][0] - mn0,     s[2 * ks][1] - mn0));
                ph[1] = ex2_h2(pack_h2(s[2 * ks][2] - mn1,     s[2 * ks][3] - mn1));
                ph[2] = ex2_h2(pack_h2(s[2 * ks + 1][0] - mn0, s[2 * ks + 1][1] - mn0));
                ph[3] = ex2_h2(pack_h2(s[2 * ks + 1][2] - mn1, s[2 * ks + 1][3] - mn1));

                MMA_F16(lsum, ph, ONES_H2, ONES_H2);   // exact fp32 row sums

                const int vrow = 16 * ks + (l & 15);
#pragma unroll
                for (int dtp = 0; dtp < 4; dtp++) {
                    uint32_t vf[4];
                    LDMX4T(vf, st + A_VF + aphys(vrow, 2 * dtp + (l >> 4)));
                    MMA_F16(O[2 * dtp + 0], ph, vf[0], vf[1]);
                    MMA_F16(O[2 * dtp + 1], ph, vf[2], vf[3]);
                }
            }
        }

        // ---- epilogue: ctx fp16 ----
        const float i0 = rcp(lsum[0]);
        const float i1 = rcp(lsum[2]);
        const int rg0 = q0 + 16 * w + (l >> 2);
        const int cb = h * 64 + 2 * (l & 3);
#pragma unroll
        for (int nt = 0; nt < 8; nt++) {
            const size_t o0 = (size_t)rg0 * 1024 + cb + nt * 8;
            const size_t o1 = (size_t)(rg0 + 8) * 1024 + cb + nt * 8;
            *(uint32_t*)(g_c + o0) = pack_h2(O[nt][0] * i0, O[nt][1] * i0);
            *(uint32_t*)(g_c + o1) = pack_h2(O[nt][2] * i1, O[nt][3] * i1);
        }
        // Barrier between halves: all warps must finish reading the last KV
        // stage before the next half's prologue overwrites both stages.
        __syncthreads();
    }
}

// ---------------------------------------------------------------------------
extern "C" void kernel_launch(void* const* d_in, const int* in_sizes, int n_in,
                              void* d_out, int out_size)
{
    const float* x  = (const float*)d_in[0];
    const float* Wq = (const float*)d_in[1];
    const float* Wk = (const float*)d_in[2];
    const float* Wv = (const float*)d_in[3];
    const float* Wo = (const float*)d_in[4];
    const float* bo = (const float*)d_in[5];
    float* out = (float*)d_out;

    const int NW = D_MODEL * D_MODEL;     // 1M

    conv_all_kernel<<<dim3(NW / 1024, 8), 256>>>(x, Wq, Wk, Wv, Wo);

    cudaFuncSetAttribute(gemm_qkv_kernel, cudaFuncAttributeMaxDynamicSharedMemorySize, GSMEM);
    cudaFuncSetAttribute(gemm_out_kernel, cudaFuncAttributeMaxDynamicSharedMemorySize, GSMEM);

    gemm_qkv_kernel<<<dim3(24, 32), 256, GSMEM>>>();

    cudaFuncSetAttribute(attn_kernel, cudaFuncAttributeMaxDynamicSharedMemorySize, A_SMEM);
    attn_kernel<<<dim3(32, N_HEADS), 128, A_SMEM>>>();

    gemm_out_kernel<<<dim3(8, 32), 256, GSMEM>>>(bo, out);
}